// round 2
// baseline (speedup 1.0000x reference)
#include <cuda_runtime.h>
#include <math.h>

// AttentionCIDNN: MLP(2->32->64->64) per row, per-64-row-block gram matrix +
// odd softmax, scattered as diagonal 64x64 blocks into an 8192x8192 fp32 output.
//
// Bottleneck analysis: output is 256MB and must be fully written (poisoned) ->
// HBM-store-bound, floor ~33us @ 8TB/s. Compute is ~170 MFLOP (noise).
// One fused kernel: 128 compute CTAs write diagonal blocks; remaining CTAs
// zero everything else (disjoint writes, full overlap).

#define BS        8192
#define BLK       64
#define NB        128
#define EPS_      1e-7f
#define NTHREADS  256
#define NZBLK     464          // total grid = 128 + 464 = 592 = 4 * 148 SMs
#define ROWPAD    72           // h row padding (16B-aligned rows, conflict-friendly)

__global__ __launch_bounds__(NTHREADS) void attention_cidnn_kernel(
    const float* __restrict__ x,        // (8192, 8, 2)
    const float* __restrict__ W1,       // (2, 32)
    const float* __restrict__ b1,       // (32,)
    const float* __restrict__ W2,       // (32, 64)
    const float* __restrict__ b2,       // (64,)
    const float* __restrict__ W3,       // (64, 64)
    const float* __restrict__ b3,       // (64,)
    const int*   __restrict__ sub_batches, // (128, 2) int32
    float* __restrict__ out)            // (8192, 8192)
{
    const int tid = threadIdx.x;

    // ---------------- Zero path: all non-diagonal-block float4s ----------------
    if (blockIdx.x >= NB) {
        const long long total4 = (long long)BS * (BS / 4);          // 16,777,216
        const long long stride = (long long)(gridDim.x - NB) * NTHREADS;
        const float4 z = make_float4(0.f, 0.f, 0.f, 0.f);
        float4* __restrict__ out4 = reinterpret_cast<float4*>(out);
        for (long long idx = (long long)(blockIdx.x - NB) * NTHREADS + tid;
             idx < total4; idx += stride) {
            int row = (int)(idx >> 11);        // 2048 float4 per row
            int c4  = (int)(idx & 2047);
            if ((row >> 6) == (c4 >> 4)) continue;   // diagonal block: compute CTA owns it
            out4[idx] = z;
        }
        return;
    }

    // ---------------- Compute path: one 64-row block ----------------
    __shared__ float h1[BLK][33];          // layer-1 activations (32 + pad)
    __shared__ float hA[BLK][ROWPAD];      // layer-2 activations, later S / e
    __shared__ float hB[BLK][ROWPAD];      // final h (64-dim)
    __shared__ float mcol[BLK];            // m[i] = max_j S[i][j]
    __shared__ float dinv[BLK];            // 1 / (rowsum(e) + EPS)

    const int base = sub_batches[blockIdx.x * 2];    // start row of this block

    const int r  = tid >> 2;               // 0..63  (row handled in 4-thread groups)
    const int j0 = (tid & 3) * 16;         // 0,16,32,48 (16-wide column chunk)

    // Phase 1: layer 1 (2 -> 32, relu). One thread per row.
    if (tid < BLK) {
        const float x0 = x[(long long)(base + tid) * 16 + 14];
        const float x1 = x[(long long)(base + tid) * 16 + 15];
        #pragma unroll
        for (int k = 0; k < 32; k++) {
            float a = fmaf(x0, __ldg(&W1[k]), fmaf(x1, __ldg(&W1[32 + k]), __ldg(&b1[k])));
            h1[tid][k] = fmaxf(a, 0.f);
        }
    }
    __syncthreads();

    // Phase 2: layer 2 (32 -> 64, relu). Each thread: 16 outputs of one row.
    {
        float acc[16];
        #pragma unroll
        for (int jj = 0; jj < 16; jj++) acc[jj] = __ldg(&b2[j0 + jj]);
        #pragma unroll 4
        for (int k = 0; k < 32; k++) {
            const float hk = h1[r][k];
            #pragma unroll
            for (int jj = 0; jj < 16; jj++)
                acc[jj] = fmaf(hk, __ldg(&W2[k * 64 + j0 + jj]), acc[jj]);
        }
        #pragma unroll
        for (int jj = 0; jj < 16; jj++) hA[r][j0 + jj] = fmaxf(acc[jj], 0.f);
    }
    __syncthreads();

    // Phase 3: layer 3 (64 -> 64, no activation) -> hB.
    {
        float acc[16];
        #pragma unroll
        for (int jj = 0; jj < 16; jj++) acc[jj] = __ldg(&b3[j0 + jj]);
        #pragma unroll 4
        for (int k = 0; k < 64; k++) {
            const float hk = hA[r][k];
            #pragma unroll
            for (int jj = 0; jj < 16; jj++)
                acc[jj] = fmaf(hk, __ldg(&W3[k * 64 + j0 + jj]), acc[jj]);
        }
        #pragma unroll
        for (int jj = 0; jj < 16; jj++) hB[r][j0 + jj] = acc[jj];
    }
    __syncthreads();

    // Phase 4: S[i][j] = dot(hB[i], hB[j]) over 64 dims -> hA (overwrites layer-2 acts).
    {
        float acc[16];
        #pragma unroll
        for (int jj = 0; jj < 16; jj++) acc[jj] = 0.f;
        const float4* hi4 = reinterpret_cast<const float4*>(&hB[r][0]);
        #pragma unroll 4
        for (int c = 0; c < 16; c++) {
            const float4 a = hi4[c];
            #pragma unroll
            for (int jj = 0; jj < 16; jj++) {
                const float4 b = *reinterpret_cast<const float4*>(&hB[j0 + jj][c * 4]);
                acc[jj] = fmaf(a.x, b.x, fmaf(a.y, b.y, fmaf(a.z, b.z, fmaf(a.w, b.w, acc[jj]))));
            }
        }
        #pragma unroll
        for (int jj = 0; jj < 16; jj++) hA[r][j0 + jj] = acc[jj];
    }
    __syncthreads();

    // Phase 5: m[i] = max_j S[i][j]   (reference: attn.max(axis=2))
    if (tid < BLK) {
        float mx = -INFINITY;
        #pragma unroll 8
        for (int j = 0; j < BLK; j++) mx = fmaxf(mx, hA[tid][j]);
        mcol[tid] = mx;
    }
    __syncthreads();

    // Phase 6: e[i][j] = exp(S[i][j] - m[j]); dinv[i] = 1/(sum_j e + EPS)
    if (tid < BLK) {
        float s = 0.f;
        #pragma unroll 8
        for (int j = 0; j < BLK; j++) {
            const float e = expf(hA[tid][j] - mcol[j]);
            hA[tid][j] = e;
            s += e;
        }
        dinv[tid] = 1.f / (s + EPS_);
    }
    __syncthreads();

    // Phase 7: write the 64x64 block at (base, base), float4 stores.
    {
        const float di = dinv[r];
        float* rowp = out + (long long)(base + r) * BS + base;
        #pragma unroll
        for (int c = 0; c < 4; c++) {
            const int j = j0 + c * 4;
            float4 v;
            v.x = hA[r][j + 0] * di;
            v.y = hA[r][j + 1] * di;
            v.z = hA[r][j + 2] * di;
            v.w = hA[r][j + 3] * di;
            *reinterpret_cast<float4*>(rowp + j) = v;
        }
    }
}

extern "C" void kernel_launch(void* const* d_in, const int* in_sizes, int n_in,
                              void* d_out, int out_size) {
    const float* x   = (const float*)d_in[0];
    const float* W1  = (const float*)d_in[1];
    const float* b1  = (const float*)d_in[2];
    const float* W2  = (const float*)d_in[3];
    const float* b2  = (const float*)d_in[4];
    const float* W3  = (const float*)d_in[5];
    const float* b3  = (const float*)d_in[6];
    const int*   sb  = (const int*)d_in[7];
    float* out = (float*)d_out;

    attention_cidnn_kernel<<<NB + NZBLK, NTHREADS>>>(x, W1, b1, W2, b2, W3, b3, sb, out);
}

// round 3
// speedup vs baseline: 1.0406x; 1.0406x over previous
#include <cuda_runtime.h>
#include <math.h>

// AttentionCIDNN split into two kernels:
//  1) zero_out: max-occupancy pure-store stream of the whole 8192x8192 fp32 out.
//     (1024 thr x 296 CTAs = exactly 2 CTAs/SM, one wave, ~10 regs, no branches)
//  2) compute: 128 CTAs, one per 64-row block: MLP(2->32->64->64), gram matrix,
//     odd softmax, overwrite the diagonal 64x64 block. Runs after zeroing in
//     stream order, so the overwrite is safe.
// R1 lesson: fusing both roles pinned the zero path at 79 regs -> 3 CTAs/SM,
// 2 waves, 29% DRAM. Splitting restores a single full-occupancy store wave.

#define BS        8192
#define BLK       64
#define NB        128
#define EPS_      1e-7f

// ---------------------------------------------------------------- zero kernel
#define ZTHREADS  1024
#define ZBLOCKS   296               // 2 CTAs/SM * 148 SMs -> one full wave

__global__ __launch_bounds__(ZTHREADS, 2) void zero_out_kernel(float4* __restrict__ out4) {
    const unsigned total4 = (unsigned)BS * (BS / 4);      // 16,777,216
    const unsigned stride = ZBLOCKS * ZTHREADS;           // 303,104
    const float4 z = make_float4(0.f, 0.f, 0.f, 0.f);
    unsigned idx = blockIdx.x * ZTHREADS + threadIdx.x;
    // 16.7M / 303k = 55.36 iterations; unroll 4 for independent in-flight stores
    unsigned end4 = total4 - 4u * stride;
    for (; idx <= end4; idx += 4u * stride) {
        out4[idx] = z;
        out4[idx + stride] = z;
        out4[idx + 2u * stride] = z;
        out4[idx + 3u * stride] = z;
    }
    for (; idx < total4; idx += stride) out4[idx] = z;
}

// ------------------------------------------------------------- compute kernel
#define CTHREADS  256
#define ROWPAD    72

__global__ __launch_bounds__(CTHREADS) void compute_blocks_kernel(
    const float* __restrict__ x,        // (8192, 8, 2)
    const float* __restrict__ W1,       // (2, 32)
    const float* __restrict__ b1,       // (32,)
    const float* __restrict__ W2,       // (32, 64)
    const float* __restrict__ b2,       // (64,)
    const float* __restrict__ W3,       // (64, 64)
    const float* __restrict__ b3,       // (64,)
    const int*   __restrict__ sub_batches, // (128, 2) int32
    float* __restrict__ out)            // (8192, 8192)
{
    const int tid = threadIdx.x;

    __shared__ float h1[BLK][33];          // layer-1 activations (32 + pad)
    __shared__ float hA[BLK][ROWPAD];      // layer-2 acts, later S / e
    __shared__ float hB[BLK][ROWPAD];      // final h (64-dim)
    __shared__ float mcol[BLK];            // m[i] = max_j S[i][j]
    __shared__ float dinv[BLK];            // 1 / (rowsum(e) + EPS)

    const int base = sub_batches[blockIdx.x * 2];

    const int r  = tid >> 2;               // 0..63
    const int j0 = (tid & 3) * 16;         // 0,16,32,48

    // Phase 1: layer 1 (2 -> 32, relu). One thread per row.
    if (tid < BLK) {
        const float x0 = x[(long long)(base + tid) * 16 + 14];
        const float x1 = x[(long long)(base + tid) * 16 + 15];
        #pragma unroll
        for (int k = 0; k < 32; k++) {
            float a = fmaf(x0, __ldg(&W1[k]), fmaf(x1, __ldg(&W1[32 + k]), __ldg(&b1[k])));
            h1[tid][k] = fmaxf(a, 0.f);
        }
    }
    __syncthreads();

    // Phase 2: layer 2 (32 -> 64, relu). Each thread: 16 outputs of one row.
    {
        float acc[16];
        #pragma unroll
        for (int jj = 0; jj < 16; jj++) acc[jj] = __ldg(&b2[j0 + jj]);
        #pragma unroll 4
        for (int k = 0; k < 32; k++) {
            const float hk = h1[r][k];
            #pragma unroll
            for (int jj = 0; jj < 16; jj++)
                acc[jj] = fmaf(hk, __ldg(&W2[k * 64 + j0 + jj]), acc[jj]);
        }
        #pragma unroll
        for (int jj = 0; jj < 16; jj++) hA[r][j0 + jj] = fmaxf(acc[jj], 0.f);
    }
    __syncthreads();

    // Phase 3: layer 3 (64 -> 64) -> hB.
    {
        float acc[16];
        #pragma unroll
        for (int jj = 0; jj < 16; jj++) acc[jj] = __ldg(&b3[j0 + jj]);
        #pragma unroll 4
        for (int k = 0; k < 64; k++) {
            const float hk = hA[r][k];
            #pragma unroll
            for (int jj = 0; jj < 16; jj++)
                acc[jj] = fmaf(hk, __ldg(&W3[k * 64 + j0 + jj]), acc[jj]);
        }
        #pragma unroll
        for (int jj = 0; jj < 16; jj++) hB[r][j0 + jj] = acc[jj];
    }
    __syncthreads();

    // Phase 4: S[i][j] = dot(hB[i], hB[j]) -> hA.
    {
        float acc[16];
        #pragma unroll
        for (int jj = 0; jj < 16; jj++) acc[jj] = 0.f;
        const float4* hi4 = reinterpret_cast<const float4*>(&hB[r][0]);
        #pragma unroll 4
        for (int c = 0; c < 16; c++) {
            const float4 a = hi4[c];
            #pragma unroll
            for (int jj = 0; jj < 16; jj++) {
                const float4 b = *reinterpret_cast<const float4*>(&hB[j0 + jj][c * 4]);
                acc[jj] = fmaf(a.x, b.x, fmaf(a.y, b.y, fmaf(a.z, b.z, fmaf(a.w, b.w, acc[jj]))));
            }
        }
        #pragma unroll
        for (int jj = 0; jj < 16; jj++) hA[r][j0 + jj] = acc[jj];
    }
    __syncthreads();

    // Phase 5: m[i] = max_j S[i][j]
    if (tid < BLK) {
        float mx = -INFINITY;
        #pragma unroll 8
        for (int j = 0; j < BLK; j++) mx = fmaxf(mx, hA[tid][j]);
        mcol[tid] = mx;
    }
    __syncthreads();

    // Phase 6: e[i][j] = exp(S[i][j] - m[j]); dinv[i] = 1/(sum_j e + EPS)
    if (tid < BLK) {
        float s = 0.f;
        #pragma unroll 8
        for (int j = 0; j < BLK; j++) {
            const float e = expf(hA[tid][j] - mcol[j]);
            hA[tid][j] = e;
            s += e;
        }
        dinv[tid] = 1.f / (s + EPS_);
    }
    __syncthreads();

    // Phase 7: overwrite the 64x64 diagonal block at (base, base).
    {
        const float di = dinv[r];
        float* rowp = out + (long long)(base + r) * BS + base;
        #pragma unroll
        for (int c = 0; c < 4; c++) {
            const int j = j0 + c * 4;
            float4 v;
            v.x = hA[r][j + 0] * di;
            v.y = hA[r][j + 1] * di;
            v.z = hA[r][j + 2] * di;
            v.w = hA[r][j + 3] * di;
            *reinterpret_cast<float4*>(rowp + j) = v;
        }
    }
}

extern "C" void kernel_launch(void* const* d_in, const int* in_sizes, int n_in,
                              void* d_out, int out_size) {
    const float* x   = (const float*)d_in[0];
    const float* W1  = (const float*)d_in[1];
    const float* b1  = (const float*)d_in[2];
    const float* W2  = (const float*)d_in[3];
    const float* b2  = (const float*)d_in[4];
    const float* W3  = (const float*)d_in[5];
    const float* b3  = (const float*)d_in[6];
    const int*   sb  = (const int*)d_in[7];
    float* out = (float*)d_out;

    zero_out_kernel<<<ZBLOCKS, ZTHREADS>>>(reinterpret_cast<float4*>(out));
    compute_blocks_kernel<<<NB, CTHREADS>>>(x, W1, b1, W2, b2, W3, b3, sb, out);
}

// round 4
// speedup vs baseline: 1.6902x; 1.6242x over previous
#include <cuda_runtime.h>
#include <math.h>

// AttentionCIDNN:
//  kernel 1: zero_out — full-occupancy float4 stream-store of all 256MB (43.9us measured).
//  kernel 2: compute  — 128 CTAs x 512 thr; smem-staged MLP(2->32->64->64), gram
//            matrix with XOR-swizzled smem, register softmax, overwrite the 128
//            diagonal 64x64 blocks. R2's version was 46.7us (scalar LDG storm +
//            bank conflicts); this one targets ~5us (FFMA-bound, 2x4 reg tiles).

#define BS        8192
#define BLK       64
#define NB        128
#define EPS_      1e-7f

// ---------------------------------------------------------------- zero kernel
#define ZTHREADS  1024
#define ZBLOCKS   296               // 2 CTAs/SM * 148 SMs -> one full wave

__global__ __launch_bounds__(ZTHREADS, 2) void zero_out_kernel(float4* __restrict__ out4) {
    const unsigned total4 = (unsigned)BS * (BS / 4);      // 16,777,216
    const unsigned stride = ZBLOCKS * ZTHREADS;           // 303,104
    const float4 z = make_float4(0.f, 0.f, 0.f, 0.f);
    unsigned idx = blockIdx.x * ZTHREADS + threadIdx.x;
    unsigned end4 = total4 - 4u * stride;
    for (; idx <= end4; idx += 4u * stride) {
        out4[idx] = z;
        out4[idx + stride] = z;
        out4[idx + 2u * stride] = z;
        out4[idx + 3u * stride] = z;
    }
    for (; idx < total4; idx += stride) out4[idx] = z;
}

// ------------------------------------------------------------- compute kernel
#define CTHREADS  512

union Region1 {                       // 16 KB, time-multiplexed
    struct { float W2s[32][64]; float h1[64][32]; } p2;   // phases 1-2
    float W3s[64][64];                                     // phase 3
    float Ss[64][64];                                      // phases 6-7
};
union Region2 {                       // 16 KB
    float h2[64][64];                 // phases 2-3
    float mcol[64];                   // phases 5-6
};

__global__ __launch_bounds__(CTHREADS) void compute_blocks_kernel(
    const float* __restrict__ x,        // (8192, 8, 2)
    const float* __restrict__ W1,       // (2, 32)
    const float* __restrict__ b1,       // (32,)
    const float* __restrict__ W2,       // (32, 64)
    const float* __restrict__ b2,       // (64,)
    const float* __restrict__ W3,       // (64, 64)
    const float* __restrict__ b3,       // (64,)
    const int*   __restrict__ sub_batches, // (128, 2)
    float* __restrict__ out)            // (8192, 8192)
{
    __shared__ Region1 R1_;
    __shared__ Region2 R2_;
    __shared__ float   h3s[64][64];     // XOR-swizzled: [r][ (c4^(r&7))*4 + (c&3) ]

    const int tid = threadIdx.x;
    const int cg  = tid & 15;           // column group (16)
    const int rg  = tid >> 4;           // row group (32)
    const int r0  = rg * 2;             // rows r0, r0+1
    const int j0  = cg * 4;             // contiguous cols j0..j0+3 (phases 2,3,7)

    const int base = sub_batches[blockIdx.x * 2];

    // ---- stage W2 into smem (512 float4 = 1/thread, coalesced) + phase 1 ----
    ((float4*)R1_.p2.W2s)[tid] = __ldg(((const float4*)W2) + tid);
    {
        const int r  = tid >> 3;                 // 0..63
        const int c0 = (tid & 7) * 4;            // 0..28
        const float x0 = __ldg(&x[(base + r) * 16 + 14]);
        const float x1 = __ldg(&x[(base + r) * 16 + 15]);
        const float4 w0 = __ldg((const float4*)&W1[c0]);
        const float4 w1 = __ldg((const float4*)&W1[32 + c0]);
        const float4 bb = __ldg((const float4*)&b1[c0]);
        float4 h;
        h.x = fmaxf(fmaf(x0, w0.x, fmaf(x1, w1.x, bb.x)), 0.f);
        h.y = fmaxf(fmaf(x0, w0.y, fmaf(x1, w1.y, bb.y)), 0.f);
        h.z = fmaxf(fmaf(x0, w0.z, fmaf(x1, w1.z, bb.z)), 0.f);
        h.w = fmaxf(fmaf(x0, w0.w, fmaf(x1, w1.w, bb.w)), 0.f);
        *(float4*)&R1_.p2.h1[r][c0] = h;
    }
    __syncthreads();

    // ---- phase 2: h2 = relu(h1 @ W2 + b2), 2x4 tile ----
    {
        float acc[2][4];
        const float4 bb = __ldg((const float4*)&b2[j0]);
        acc[0][0] = bb.x; acc[0][1] = bb.y; acc[0][2] = bb.z; acc[0][3] = bb.w;
        acc[1][0] = bb.x; acc[1][1] = bb.y; acc[1][2] = bb.z; acc[1][3] = bb.w;
        #pragma unroll
        for (int k = 0; k < 32; k += 4) {
            const float4 a0 = *(const float4*)&R1_.p2.h1[r0][k];
            const float4 a1 = *(const float4*)&R1_.p2.h1[r0 + 1][k];
            const float a0v[4] = {a0.x, a0.y, a0.z, a0.w};
            const float a1v[4] = {a1.x, a1.y, a1.z, a1.w};
            #pragma unroll
            for (int i = 0; i < 4; i++) {
                const float4 w = *(const float4*)&R1_.p2.W2s[k + i][j0];
                acc[0][0] = fmaf(a0v[i], w.x, acc[0][0]);
                acc[0][1] = fmaf(a0v[i], w.y, acc[0][1]);
                acc[0][2] = fmaf(a0v[i], w.z, acc[0][2]);
                acc[0][3] = fmaf(a0v[i], w.w, acc[0][3]);
                acc[1][0] = fmaf(a1v[i], w.x, acc[1][0]);
                acc[1][1] = fmaf(a1v[i], w.y, acc[1][1]);
                acc[1][2] = fmaf(a1v[i], w.z, acc[1][2]);
                acc[1][3] = fmaf(a1v[i], w.w, acc[1][3]);
            }
        }
        float4 o0, o1;
        o0.x = fmaxf(acc[0][0], 0.f); o0.y = fmaxf(acc[0][1], 0.f);
        o0.z = fmaxf(acc[0][2], 0.f); o0.w = fmaxf(acc[0][3], 0.f);
        o1.x = fmaxf(acc[1][0], 0.f); o1.y = fmaxf(acc[1][1], 0.f);
        o1.z = fmaxf(acc[1][2], 0.f); o1.w = fmaxf(acc[1][3], 0.f);
        *(float4*)&R2_.h2[r0][j0]     = o0;
        *(float4*)&R2_.h2[r0 + 1][j0] = o1;
    }
    __syncthreads();

    // ---- stage W3 over the dead W2s/h1 region ----
    ((float4*)R1_.W3s)[tid]       = __ldg(((const float4*)W3) + tid);
    ((float4*)R1_.W3s)[tid + 512] = __ldg(((const float4*)W3) + tid + 512);
    __syncthreads();

    // ---- phase 3: h3 = h2 @ W3 + b3 -> XOR-swizzled h3s ----
    {
        float acc[2][4];
        const float4 bb = __ldg((const float4*)&b3[j0]);
        acc[0][0] = bb.x; acc[0][1] = bb.y; acc[0][2] = bb.z; acc[0][3] = bb.w;
        acc[1][0] = bb.x; acc[1][1] = bb.y; acc[1][2] = bb.z; acc[1][3] = bb.w;
        #pragma unroll 4
        for (int k = 0; k < 64; k += 4) {
            const float4 a0 = *(const float4*)&R2_.h2[r0][k];
            const float4 a1 = *(const float4*)&R2_.h2[r0 + 1][k];
            const float a0v[4] = {a0.x, a0.y, a0.z, a0.w};
            const float a1v[4] = {a1.x, a1.y, a1.z, a1.w};
            #pragma unroll
            for (int i = 0; i < 4; i++) {
                const float4 w = *(const float4*)&R1_.W3s[k + i][j0];
                acc[0][0] = fmaf(a0v[i], w.x, acc[0][0]);
                acc[0][1] = fmaf(a0v[i], w.y, acc[0][1]);
                acc[0][2] = fmaf(a0v[i], w.z, acc[0][2]);
                acc[0][3] = fmaf(a0v[i], w.w, acc[0][3]);
                acc[1][0] = fmaf(a1v[i], w.x, acc[1][0]);
                acc[1][1] = fmaf(a1v[i], w.y, acc[1][1]);
                acc[1][2] = fmaf(a1v[i], w.z, acc[1][2]);
                acc[1][3] = fmaf(a1v[i], w.w, acc[1][3]);
            }
        }
        float4 o0 = make_float4(acc[0][0], acc[0][1], acc[0][2], acc[0][3]);
        float4 o1 = make_float4(acc[1][0], acc[1][1], acc[1][2], acc[1][3]);
        const int s0 = (cg ^ (r0 & 7)) * 4;
        const int s1 = (cg ^ ((r0 + 1) & 7)) * 4;
        *(float4*)&h3s[r0][s0]     = o0;
        *(float4*)&h3s[r0 + 1][s1] = o1;
    }
    __syncthreads();

    // ---- phase 4: S[r][j] = dot(h3[r], h3[j]); cols strided j = cg + 16q ----
    float s4[2][4];
    #pragma unroll
    for (int q = 0; q < 4; q++) { s4[0][q] = 0.f; s4[1][q] = 0.f; }
    #pragma unroll 4
    for (int c4 = 0; c4 < 16; c4++) {
        const float4 a0 = *(const float4*)&h3s[r0][(c4 ^ (r0 & 7)) * 4];
        const float4 a1 = *(const float4*)&h3s[r0 + 1][(c4 ^ ((r0 + 1) & 7)) * 4];
        const int sb = (c4 ^ (cg & 7)) * 4;
        #pragma unroll
        for (int q = 0; q < 4; q++) {
            const float4 b = *(const float4*)&h3s[cg + 16 * q][sb];
            s4[0][q] = fmaf(a0.x, b.x, fmaf(a0.y, b.y, fmaf(a0.z, b.z, fmaf(a0.w, b.w, s4[0][q]))));
            s4[1][q] = fmaf(a1.x, b.x, fmaf(a1.y, b.y, fmaf(a1.z, b.z, fmaf(a1.w, b.w, s4[1][q]))));
        }
    }

    // ---- phase 5: m[r] = max_j S[r][j] (register + half-warp shfl reduce) ----
    float mx0 = fmaxf(fmaxf(s4[0][0], s4[0][1]), fmaxf(s4[0][2], s4[0][3]));
    float mx1 = fmaxf(fmaxf(s4[1][0], s4[1][1]), fmaxf(s4[1][2], s4[1][3]));
    #pragma unroll
    for (int d = 1; d < 16; d <<= 1) {
        mx0 = fmaxf(mx0, __shfl_xor_sync(0xffffffffu, mx0, d));
        mx1 = fmaxf(mx1, __shfl_xor_sync(0xffffffffu, mx1, d));
    }
    __syncthreads();                       // h2 region dead -> reuse for mcol
    if (cg == 0) { R2_.mcol[r0] = mx0; R2_.mcol[r0 + 1] = mx1; }
    __syncthreads();

    // ---- phase 6: e = exp(S - m[col]); rowsum; scale; stash in Ss ----
    {
        float mj[4];
        #pragma unroll
        for (int q = 0; q < 4; q++) mj[q] = R2_.mcol[cg + 16 * q];
        float e0[4], e1[4], sum0 = 0.f, sum1 = 0.f;
        #pragma unroll
        for (int q = 0; q < 4; q++) {
            e0[q] = __expf(s4[0][q] - mj[q]);
            e1[q] = __expf(s4[1][q] - mj[q]);
            sum0 += e0[q]; sum1 += e1[q];
        }
        #pragma unroll
        for (int d = 1; d < 16; d <<= 1) {
            sum0 += __shfl_xor_sync(0xffffffffu, sum0, d);
            sum1 += __shfl_xor_sync(0xffffffffu, sum1, d);
        }
        const float di0 = 1.f / (sum0 + EPS_);
        const float di1 = 1.f / (sum1 + EPS_);
        #pragma unroll
        for (int q = 0; q < 4; q++) {
            R1_.Ss[r0][cg + 16 * q]     = e0[q] * di0;
            R1_.Ss[r0 + 1][cg + 16 * q] = e1[q] * di1;
        }
    }
    __syncthreads();

    // ---- phase 7: contiguous float4 store of the 64x64 block at (base, base) ----
    {
        const float4 v0 = *(const float4*)&R1_.Ss[r0][j0];
        const float4 v1 = *(const float4*)&R1_.Ss[r0 + 1][j0];
        *(float4*)(out + (long long)(base + r0) * BS + base + j0)       = v0;
        *(float4*)(out + (long long)(base + r0 + 1) * BS + base + j0)   = v1;
    }
}

extern "C" void kernel_launch(void* const* d_in, const int* in_sizes, int n_in,
                              void* d_out, int out_size) {
    const float* x   = (const float*)d_in[0];
    const float* W1  = (const float*)d_in[1];
    const float* b1  = (const float*)d_in[2];
    const float* W2  = (const float*)d_in[3];
    const float* b2  = (const float*)d_in[4];
    const float* W3  = (const float*)d_in[5];
    const float* b3  = (const float*)d_in[6];
    const int*   sb  = (const int*)d_in[7];
    float* out = (float*)d_out;

    zero_out_kernel<<<ZBLOCKS, ZTHREADS>>>(reinterpret_cast<float4*>(out));
    compute_blocks_kernel<<<NB, CTHREADS>>>(x, W1, b1, W2, b2, W3, b3, sb, out);
}

// round 5
// speedup vs baseline: 2.2084x; 1.3066x over previous
#include <cuda_runtime.h>
#include <math.h>

// AttentionCIDNN, fully fused single kernel:
//   - 592 CTAs x 512 thr = exactly 4 CTAs/SM (one wave), regs capped at 32 via
//     __launch_bounds__ so the zero path keeps R2's full-occupancy store config.
//   - CTAs [0,128): compute MLP(2->32->64->64) + gram + odd softmax, write the
//     diagonal 64x64 block, THEN join the zero work-stealing pool.
//   - All CTAs steal 32KB rows (one 8192-float row) from a global atomic
//     counter and stream zeros, skipping the 16 diagonal float4s of that row.
//   Compute (~12us) hides entirely under the HBM-store-bound zeroing (~44us).

#define BS        8192
#define BLK       64
#define NB        128
#define EPS_      1e-7f
#define NTHREADS  512
#define NCTAS     592           // 4 * 148 SMs
#define NROWS     8192u

__device__ unsigned g_zero_row;

union Region1 {                       // 16 KB, time-multiplexed
    struct { float W2s[32][64]; float h1[64][32]; } p2;   // phases 1-2
    float W3s[64][64];                                     // phase 3
    float Ss[64][64];                                      // phases 6-7
};
union Region2 {                       // 16 KB
    float h2[64][64];                 // phases 2-3
    float mcol[64];                   // phases 5-6
};

__global__ __launch_bounds__(NTHREADS, 4) void attention_fused_kernel(
    const float* __restrict__ x,        // (8192, 8, 2)
    const float* __restrict__ W1,       // (2, 32)
    const float* __restrict__ b1,       // (32,)
    const float* __restrict__ W2,       // (32, 64)
    const float* __restrict__ b2,       // (64,)
    const float* __restrict__ W3,       // (64, 64)
    const float* __restrict__ b3,       // (64,)
    const int*   __restrict__ sub_batches, // (128, 2)
    float* __restrict__ out)            // (8192, 8192)
{
    __shared__ Region1 R1_;
    __shared__ Region2 R2_;
    __shared__ float   h3s[64][64];     // XOR-swizzled: [r][(c4^(r&7))*4 + (c&3)]
    __shared__ unsigned sh_row;

    const int tid = threadIdx.x;

    if (blockIdx.x < NB) {
        // ================= compute path: one 64-row diagonal block =================
        const int cg  = tid & 15;           // column group (16)
        const int rg  = tid >> 4;           // row group (32)
        const int r0  = rg * 2;             // rows r0, r0+1
        const int j0  = cg * 4;             // contiguous cols j0..j0+3

        const int base = sub_batches[blockIdx.x * 2];

        // ---- stage W2 (512 float4, coalesced) + phase 1 (2 -> 32, relu) ----
        ((float4*)R1_.p2.W2s)[tid] = __ldg(((const float4*)W2) + tid);
        {
            const int r  = tid >> 3;                 // 0..63
            const int c0 = (tid & 7) * 4;            // 0..28
            const float x0 = __ldg(&x[(base + r) * 16 + 14]);
            const float x1 = __ldg(&x[(base + r) * 16 + 15]);
            const float4 w0 = __ldg((const float4*)&W1[c0]);
            const float4 w1 = __ldg((const float4*)&W1[32 + c0]);
            const float4 bb = __ldg((const float4*)&b1[c0]);
            float4 h;
            h.x = fmaxf(fmaf(x0, w0.x, fmaf(x1, w1.x, bb.x)), 0.f);
            h.y = fmaxf(fmaf(x0, w0.y, fmaf(x1, w1.y, bb.y)), 0.f);
            h.z = fmaxf(fmaf(x0, w0.z, fmaf(x1, w1.z, bb.z)), 0.f);
            h.w = fmaxf(fmaf(x0, w0.w, fmaf(x1, w1.w, bb.w)), 0.f);
            *(float4*)&R1_.p2.h1[r][c0] = h;
        }
        __syncthreads();

        // ---- phase 2: h2 = relu(h1 @ W2 + b2), 2x4 tile ----
        {
            float acc[2][4];
            const float4 bb = __ldg((const float4*)&b2[j0]);
            acc[0][0] = bb.x; acc[0][1] = bb.y; acc[0][2] = bb.z; acc[0][3] = bb.w;
            acc[1][0] = bb.x; acc[1][1] = bb.y; acc[1][2] = bb.z; acc[1][3] = bb.w;
            #pragma unroll
            for (int k = 0; k < 32; k += 4) {
                const float4 a0 = *(const float4*)&R1_.p2.h1[r0][k];
                const float4 a1 = *(const float4*)&R1_.p2.h1[r0 + 1][k];
                const float a0v[4] = {a0.x, a0.y, a0.z, a0.w};
                const float a1v[4] = {a1.x, a1.y, a1.z, a1.w};
                #pragma unroll
                for (int i = 0; i < 4; i++) {
                    const float4 w = *(const float4*)&R1_.p2.W2s[k + i][j0];
                    acc[0][0] = fmaf(a0v[i], w.x, acc[0][0]);
                    acc[0][1] = fmaf(a0v[i], w.y, acc[0][1]);
                    acc[0][2] = fmaf(a0v[i], w.z, acc[0][2]);
                    acc[0][3] = fmaf(a0v[i], w.w, acc[0][3]);
                    acc[1][0] = fmaf(a1v[i], w.x, acc[1][0]);
                    acc[1][1] = fmaf(a1v[i], w.y, acc[1][1]);
                    acc[1][2] = fmaf(a1v[i], w.z, acc[1][2]);
                    acc[1][3] = fmaf(a1v[i], w.w, acc[1][3]);
                }
            }
            float4 o0, o1;
            o0.x = fmaxf(acc[0][0], 0.f); o0.y = fmaxf(acc[0][1], 0.f);
            o0.z = fmaxf(acc[0][2], 0.f); o0.w = fmaxf(acc[0][3], 0.f);
            o1.x = fmaxf(acc[1][0], 0.f); o1.y = fmaxf(acc[1][1], 0.f);
            o1.z = fmaxf(acc[1][2], 0.f); o1.w = fmaxf(acc[1][3], 0.f);
            *(float4*)&R2_.h2[r0][j0]     = o0;
            *(float4*)&R2_.h2[r0 + 1][j0] = o1;
        }
        __syncthreads();

        // ---- stage W3 over the dead W2s/h1 region ----
        ((float4*)R1_.W3s)[tid]       = __ldg(((const float4*)W3) + tid);
        ((float4*)R1_.W3s)[tid + 512] = __ldg(((const float4*)W3) + tid + 512);
        __syncthreads();

        // ---- phase 3: h3 = h2 @ W3 + b3 -> XOR-swizzled h3s ----
        {
            float acc[2][4];
            const float4 bb = __ldg((const float4*)&b3[j0]);
            acc[0][0] = bb.x; acc[0][1] = bb.y; acc[0][2] = bb.z; acc[0][3] = bb.w;
            acc[1][0] = bb.x; acc[1][1] = bb.y; acc[1][2] = bb.z; acc[1][3] = bb.w;
            #pragma unroll 4
            for (int k = 0; k < 64; k += 4) {
                const float4 a0 = *(const float4*)&R2_.h2[r0][k];
                const float4 a1 = *(const float4*)&R2_.h2[r0 + 1][k];
                const float a0v[4] = {a0.x, a0.y, a0.z, a0.w};
                const float a1v[4] = {a1.x, a1.y, a1.z, a1.w};
                #pragma unroll
                for (int i = 0; i < 4; i++) {
                    const float4 w = *(const float4*)&R1_.W3s[k + i][j0];
                    acc[0][0] = fmaf(a0v[i], w.x, acc[0][0]);
                    acc[0][1] = fmaf(a0v[i], w.y, acc[0][1]);
                    acc[0][2] = fmaf(a0v[i], w.z, acc[0][2]);
                    acc[0][3] = fmaf(a0v[i], w.w, acc[0][3]);
                    acc[1][0] = fmaf(a1v[i], w.x, acc[1][0]);
                    acc[1][1] = fmaf(a1v[i], w.y, acc[1][1]);
                    acc[1][2] = fmaf(a1v[i], w.z, acc[1][2]);
                    acc[1][3] = fmaf(a1v[i], w.w, acc[1][3]);
                }
            }
            const int s0 = (cg ^ (r0 & 7)) * 4;
            const int s1 = (cg ^ ((r0 + 1) & 7)) * 4;
            *(float4*)&h3s[r0][s0]     = make_float4(acc[0][0], acc[0][1], acc[0][2], acc[0][3]);
            *(float4*)&h3s[r0 + 1][s1] = make_float4(acc[1][0], acc[1][1], acc[1][2], acc[1][3]);
        }
        __syncthreads();

        // ---- phase 4: S[r][j] = dot(h3[r], h3[j]); cols j = cg + 16q ----
        float s4[2][4];
        #pragma unroll
        for (int q = 0; q < 4; q++) { s4[0][q] = 0.f; s4[1][q] = 0.f; }
        #pragma unroll 4
        for (int c4 = 0; c4 < 16; c4++) {
            const float4 a0 = *(const float4*)&h3s[r0][(c4 ^ (r0 & 7)) * 4];
            const float4 a1 = *(const float4*)&h3s[r0 + 1][(c4 ^ ((r0 + 1) & 7)) * 4];
            const int sb = (c4 ^ (cg & 7)) * 4;
            #pragma unroll
            for (int q = 0; q < 4; q++) {
                const float4 b = *(const float4*)&h3s[cg + 16 * q][sb];
                s4[0][q] = fmaf(a0.x, b.x, fmaf(a0.y, b.y, fmaf(a0.z, b.z, fmaf(a0.w, b.w, s4[0][q]))));
                s4[1][q] = fmaf(a1.x, b.x, fmaf(a1.y, b.y, fmaf(a1.z, b.z, fmaf(a1.w, b.w, s4[1][q]))));
            }
        }

        // ---- phase 5: m[r] = max_j S[r][j] (half-warp shfl reduce) ----
        float mx0 = fmaxf(fmaxf(s4[0][0], s4[0][1]), fmaxf(s4[0][2], s4[0][3]));
        float mx1 = fmaxf(fmaxf(s4[1][0], s4[1][1]), fmaxf(s4[1][2], s4[1][3]));
        #pragma unroll
        for (int d = 1; d < 16; d <<= 1) {
            mx0 = fmaxf(mx0, __shfl_xor_sync(0xffffffffu, mx0, d));
            mx1 = fmaxf(mx1, __shfl_xor_sync(0xffffffffu, mx1, d));
        }
        __syncthreads();                       // h2 region dead -> reuse for mcol
        if (cg == 0) { R2_.mcol[r0] = mx0; R2_.mcol[r0 + 1] = mx1; }
        __syncthreads();

        // ---- phase 6: e = exp(S - m[col]); rowsum; scale; stash in Ss ----
        {
            float mj[4];
            #pragma unroll
            for (int q = 0; q < 4; q++) mj[q] = R2_.mcol[cg + 16 * q];
            float e0[4], e1[4], sum0 = 0.f, sum1 = 0.f;
            #pragma unroll
            for (int q = 0; q < 4; q++) {
                e0[q] = __expf(s4[0][q] - mj[q]);
                e1[q] = __expf(s4[1][q] - mj[q]);
                sum0 += e0[q]; sum1 += e1[q];
            }
            #pragma unroll
            for (int d = 1; d < 16; d <<= 1) {
                sum0 += __shfl_xor_sync(0xffffffffu, sum0, d);
                sum1 += __shfl_xor_sync(0xffffffffu, sum1, d);
            }
            const float di0 = 1.f / (sum0 + EPS_);
            const float di1 = 1.f / (sum1 + EPS_);
            #pragma unroll
            for (int q = 0; q < 4; q++) {
                R1_.Ss[r0][cg + 16 * q]     = e0[q] * di0;
                R1_.Ss[r0 + 1][cg + 16 * q] = e1[q] * di1;
            }
        }
        __syncthreads();

        // ---- phase 7: contiguous float4 store of the 64x64 block ----
        {
            const float4 v0 = *(const float4*)&R1_.Ss[r0][j0];
            const float4 v1 = *(const float4*)&R1_.Ss[r0 + 1][j0];
            *(float4*)(out + (long long)(base + r0) * BS + base + j0)     = v0;
            *(float4*)(out + (long long)(base + r0 + 1) * BS + base + j0) = v1;
        }
        // fall through into the zero-stealing pool
    }

    // ================= zero path: steal 32KB rows, skip diagonal float4s =================
    {
        float4* __restrict__ out4 = reinterpret_cast<float4*>(out);
        const float4 z = make_float4(0.f, 0.f, 0.f, 0.f);
        for (;;) {
            __syncthreads();
            if (tid == 0) sh_row = atomicAdd(&g_zero_row, 1u);
            __syncthreads();
            const unsigned row = sh_row;
            if (row >= NROWS) break;
            const unsigned blkr = row >> 6;            // diagonal block index of this row
            float4* __restrict__ rp = out4 + (size_t)row * (BS / 4);
            #pragma unroll
            for (int s = 0; s < 4; s++) {
                const unsigned i = (unsigned)tid + s * NTHREADS;
                if ((i >> 4) != blkr) rp[i] = z;       // skip the 16 diagonal float4s
            }
        }
    }
}

extern "C" void kernel_launch(void* const* d_in, const int* in_sizes, int n_in,
                              void* d_out, int out_size) {
    const float* x   = (const float*)d_in[0];
    const float* W1  = (const float*)d_in[1];
    const float* b1  = (const float*)d_in[2];
    const float* W2  = (const float*)d_in[3];
    const float* b2  = (const float*)d_in[4];
    const float* W3  = (const float*)d_in[5];
    const float* b3  = (const float*)d_in[6];
    const int*   sb  = (const int*)d_in[7];
    float* out = (float*)d_out;

    void* cptr = nullptr;
    cudaGetSymbolAddress(&cptr, g_zero_row);
    cudaMemsetAsync(cptr, 0, sizeof(unsigned), 0);

    attention_fused_kernel<<<NCTAS, NTHREADS>>>(x, W1, b1, W2, b2, W3, b3, sb, out);
}